// round 1
// baseline (speedup 1.0000x reference)
#include <cuda_runtime.h>

// ConvNearestNeightbor: out[b, n*C+c, h, w] = max_{k=(row,col)} |x_pad[b,c,h-row,w-col] - nb[n,c,k]|
// B=16, C=32, H=W=32, NUM=32. Issue-bound: ~300M FADD/FMNMX minimum.

namespace {

constexpr int B = 16, C = 32, H = 32, W = 32, NUM = 32;
constexpr int HW = H * W;
constexpr int NSPLIT = 2;            // split NUM across blocks for wave balance
constexpr int NPER = NUM / NSPLIT;   // 16 codebook entries per block

__global__ __launch_bounds__(256) void cnn_kernel(
    const float* __restrict__ x,
    const float* __restrict__ nb,
    float* __restrict__ out) {
  __shared__ __align__(16) float xs[34 * 36];      // 34x34 halo tile, padded rows
  __shared__ __align__(16) float nbs[NPER * 12];   // 9 floats padded to 12 for LDS.128

  const int bc = blockIdx.x;        // 0 .. B*C-1
  const int ns = blockIdx.y;        // 0 .. NSPLIT-1
  const int c  = bc & (C - 1);
  const int b  = bc / C;
  const int tid = threadIdx.x;

  // ---- load x tile with zero halo ----
  const float* xp = x + (size_t)bc * HW;
  for (int i = tid; i < 34 * 34; i += 256) {
    int r  = i / 34;
    int cc = i - r * 34;
    int gh = r - 1, gw = cc - 1;
    float v = 0.f;
    if ((unsigned)gh < (unsigned)H && (unsigned)gw < (unsigned)W)
      v = xp[gh * W + gw];
    xs[r * 36 + cc] = v;
  }
  // ---- load neighbors for this c, this n-split ----
  for (int i = tid; i < NPER * 9; i += 256) {
    int nn = i / 9;
    int k  = i - nn * 9;
    nbs[nn * 12 + k] = nb[(size_t)(ns * NPER + nn) * (C * 9) + c * 9 + k];
  }
  __syncthreads();

  // thread -> 4 consecutive w outputs at row h
  const int h  = tid >> 3;           // 0..31
  const int wq = (tid & 7) << 2;     // 0,4,...,28

  // hoist the 3x6 x-window into registers: reused for all NPER codebook rows.
  // out(h, wq+j) with shift (row,col) reads xs[h + (1-row)][wq + j + (1-col)]
  float xv[3][6];
#pragma unroll
  for (int r = 0; r < 3; r++) {
    const float* p = &xs[(h + r) * 36 + wq];
    float4 v4 = *(const float4*)p;
    float2 v2 = *(const float2*)(p + 4);
    xv[r][0] = v4.x; xv[r][1] = v4.y; xv[r][2] = v4.z; xv[r][3] = v4.w;
    xv[r][4] = v2.x; xv[r][5] = v2.y;
  }

  float* outp = out + ((size_t)(b * NUM + ns * NPER) * C + c) * HW + h * W + wq;

#pragma unroll 2
  for (int nn = 0; nn < NPER; nn++) {
    float4 n0 = *(const float4*)&nbs[nn * 12];
    float4 n1 = *(const float4*)&nbs[nn * 12 + 4];
    float  n8 = nbs[nn * 12 + 8];
    float nv[9] = {n0.x, n0.y, n0.z, n0.w, n1.x, n1.y, n1.z, n1.w, n8};

    float acc0 = 0.f, acc1 = 0.f, acc2 = 0.f, acc3 = 0.f;
#pragma unroll
    for (int r = 0; r < 3; r++) {       // r = 1 - row  (row = 1-r)
#pragma unroll
      for (int cc = 0; cc < 3; cc++) {  // cc = 1 - col
        const int k = (2 - r) * 3 + (2 - cc);  // k = (row+1)*3 + (col+1)
        const float nk = nv[k];
        acc0 = fmaxf(acc0, fabsf(xv[r][cc + 0] - nk));
        acc1 = fmaxf(acc1, fabsf(xv[r][cc + 1] - nk));
        acc2 = fmaxf(acc2, fabsf(xv[r][cc + 2] - nk));
        acc3 = fmaxf(acc3, fabsf(xv[r][cc + 3] - nk));
      }
    }
    *(float4*)outp = make_float4(acc0, acc1, acc2, acc3);
    outp += (size_t)C * HW;  // next n: channel index advances by C
  }
}

}  // namespace

extern "C" void kernel_launch(void* const* d_in, const int* in_sizes, int n_in,
                              void* d_out, int out_size) {
  const float* x  = (const float*)d_in[0];   // (B,C,H,W) fp32
  const float* nb = (const float*)d_in[1];   // (NUM,C,9) fp32
  float* out = (float*)d_out;                // (B, NUM*C, H, W) fp32
  dim3 grid(B * C, NSPLIT);
  cnn_kernel<<<grid, 256>>>(x, nb, out);
}